// round 6
// baseline (speedup 1.0000x reference)
#include <cuda_runtime.h>

// 2-layer LSTM (H=50), T=65536 serial steps, one persistent CTA, 256 threads.
// Homogeneous R5 skeleton, restructured to shorten barrier-to-barrier chains:
//   P_A gates: y(s-1)-dot, err update, g1 = a1p + w7*err, ACTIVATE, -> sg
//   P_B gates: q = bb2 + W_hh2 @ h2(s-1)   || units: cell1 -> h1(s)
//   P_C gates: g2 = q + W_ih2 @ h1(s), ACTIVATE, -> sg
//   P_D gates: a1p(s+1) = bb1 + W_ih1@x(s+1) + W_hh1@h1(s)  (private reg)
//              || units: cell2 -> h2(s)
// Activations are applied by the 200 gate threads (1 predicated MUFU each),
// so unit phases are short; a1p lives in the producing thread's register.

#define HDIM     50
#define INP      8
#define CHUNK    1024
#define NTHREADS 256

typedef unsigned long long u64;

__device__ __forceinline__ u64 pk2(float lo, float hi) {
    u64 r; asm("mov.b64 %0, {%1,%2};" : "=l"(r) : "f"(lo), "f"(hi)); return r;
}
__device__ __forceinline__ float2 upk2(u64 v) {
    float2 f; asm("mov.b64 {%0,%1}, %2;" : "=f"(f.x), "=f"(f.y) : "l"(v)); return f;
}
__device__ __forceinline__ u64 ffma2(u64 a, u64 b, u64 c) {
    u64 d; asm("fma.rn.f32x2 %0, %1, %2, %3;" : "=l"(d) : "l"(a), "l"(b), "l"(c)); return d;
}
__device__ __forceinline__ float tanha(float x) {
    float r; asm("tanh.approx.f32 %0, %1;" : "=f"(r) : "f"(x)); return r;
}

__global__ __launch_bounds__(NTHREADS, 1)
void lstm_r6_kernel(const float* __restrict__ input_seq,
                    const float* __restrict__ W_ih1, const float* __restrict__ W_hh1,
                    const float* __restrict__ b_ih1, const float* __restrict__ b_hh1,
                    const float* __restrict__ W_ih2, const float* __restrict__ W_hh2,
                    const float* __restrict__ b_ih2, const float* __restrict__ b_hh2,
                    const float* __restrict__ W_out, const float* __restrict__ b_out,
                    float* __restrict__ out, int T)
{
    __shared__ __align__(16) float sh1[52];    // h1(s), [50..51]=0
    __shared__ __align__(16) float sh2[52];    // h2(s), [50..51]=0
    __shared__ __align__(16) float sg[200];    // activated gates (L1, then L2)
    __shared__ __align__(16) float swout[52];  // W_out padded
    __shared__ __align__(16) float xbuf[(CHUNK + 1) * INP];

    const int t = threadIdx.x;
    const bool gateT = (t < 200);
    const int row = gateT ? t : 0;
    const bool unitT = (t >= 200) && (t < 200 + HDIM);
    const int u = unitT ? (t - 200) : 0;

    // activation constants: rows 100..149 are the g-gate (tanh), rest sigmoid
    const bool isG = gateT && (row >= 100) && (row < 150);
    const float actK = isG ? 1.0f : 0.5f;   // pre-scale (and post-scale)
    const float actA = isG ? 0.0f : 0.5f;   // post-add
    //   act(x) = fmaf(tanha(actK*x), actK, actA)

    // ---- per-thread full-row weights (f32x2; index 25 = zero pad vs sh[50..51])
    u64 wx[3], wh1[26], wi2[26], wh2[26];
    float w6, w7, bb1, bb2;
    {
        const float* r1 = W_ih1 + row * INP;
        wx[0] = pk2(r1[0], r1[1]);
        wx[1] = pk2(r1[2], r1[3]);
        wx[2] = pk2(r1[4], r1[5]);
        w6 = r1[6]; w7 = r1[7];
        const float* r2 = W_hh1 + row * HDIM;
        const float* r3 = W_ih2 + row * HDIM;
        const float* r4 = W_hh2 + row * HDIM;
        #pragma unroll
        for (int j = 0; j < 25; ++j) {
            wh1[j] = pk2(r2[2*j], r2[2*j+1]);
            wi2[j] = pk2(r3[2*j], r3[2*j+1]);
            wh2[j] = pk2(r4[2*j], r4[2*j+1]);
        }
        wh1[25] = 0ULL; wi2[25] = 0ULL; wh2[25] = 0ULL;
        bb1 = b_ih1[row] + b_hh1[row];
        bb2 = b_ih2[row] + b_hh2[row];
    }
    const float bo = b_out[0];
    if (t < 52) {
        swout[t] = (t < HDIM) ? W_out[t] : 0.0f;
        sh1[t] = 0.0f;
        sh2[t] = 0.0f;
    }

    float c1 = 0.0f, c2 = 0.0f, err = 0.0f, x7prev = 0.0f, a1p = 0.0f;
    __syncthreads();

    #pragma unroll 1
    for (int s = 0; s < T; ++s) {
        const int lo = s & (CHUNK - 1);
        if (lo == 0) {
            // all prior xbuf readers finished at BAR_D of step s-1
            const float4* src = (const float4*)(input_seq + (size_t)s * INP);
            float4* dst = (float4*)xbuf;
            int n4 = (CHUNK + 1) * 2;
            int rem4 = (T - s) * 2;
            if (rem4 < n4) n4 = rem4;
            for (int i = t; i < n4; i += NTHREADS) dst[i] = src[i];
            __syncthreads();
            if (s == 0 && gateT) {
                // bootstrap a1p(0) = bb1 + W_ih1 @ x(0)  (h1(-1)=0, err=0)
                float4 xa = *(const float4*)(xbuf);
                float4 xb = *(const float4*)(xbuf + 4);
                u64 a0 = ffma2(wx[0], pk2(xa.x, xa.y), pk2(bb1, 0.0f));
                u64 a1 = ffma2(wx[1], pk2(xa.z, xa.w), pk2(w6 * xb.z, 0.0f));
                a0 = ffma2(wx[2], pk2(xb.x, xb.y), a0);
                float2 f0 = upk2(a0), f1 = upk2(a1);
                a1p = (f0.x + f1.x) + (f0.y + f1.y);
            }
        }

        // ---- P_A: y(s-1), err, gates1 finish + activation
        if (gateT) {
            if (s) {
                const float4* hv = (const float4*)sh2;
                const float4* wv = (const float4*)swout;
                u64 y0 = pk2(0.0f, 0.0f), y1 = pk2(0.0f, 0.0f);
                #pragma unroll
                for (int j = 0; j < 13; ++j) {
                    float4 h = hv[j];
                    float4 wq = wv[j];
                    y0 = ffma2(pk2(wq.x, wq.y), pk2(h.x, h.y), y0);
                    y1 = ffma2(pk2(wq.z, wq.w), pk2(h.z, h.w), y1);
                }
                float2 f0 = upk2(y0), f1 = upk2(y1);
                float y = bo + (f0.x + f1.x) + (f0.y + f1.y);
                err = 0.9f * err + 0.1f * (x7prev - y);
                if (t == 0) out[s - 1] = y;
            }
            float g1 = fmaf(w7, err, a1p);
            sg[row] = fmaf(tanha(actK * g1), actK, actA);
        }
        __syncthreads();   // BAR_A: activated gates1 ready

        // ---- P_B: gates compute wh2@h2(s-1) || units do cell1
        u64 q0, q1;        // carried to P_C in registers
        if (gateT) {
            q0 = pk2(bb2, 0.0f); q1 = pk2(0.0f, 0.0f);
            const float4* hv = (const float4*)sh2;
            #pragma unroll
            for (int j = 0; j < 13; ++j) {
                float4 h = hv[j];
                q0 = ffma2(wh2[2*j],     pk2(h.x, h.y), q0);
                q1 = ffma2(wh2[2*j + 1], pk2(h.z, h.w), q1);
            }
        }
        if (unitT) {
            float I = sg[u], F = sg[u + 50], G = sg[u + 100], O = sg[u + 150];
            c1 = F * c1 + I * G;
            sh1[u] = O * tanha(c1);
        }
        __syncthreads();   // BAR_B: h1(s) ready

        // ---- P_C: gates2 finish + activation
        if (gateT) {
            const float4* hv = (const float4*)sh1;
            #pragma unroll
            for (int j = 0; j < 13; ++j) {
                float4 h = hv[j];
                q0 = ffma2(wi2[2*j],     pk2(h.x, h.y), q0);
                q1 = ffma2(wi2[2*j + 1], pk2(h.z, h.w), q1);
            }
            float2 f0 = upk2(q0), f1 = upk2(q1);
            float g2 = (f0.x + f1.x) + (f0.y + f1.y);
            sg[row] = fmaf(tanha(actK * g2), actK, actA);
        }
        __syncthreads();   // BAR_C: activated gates2 ready

        // ---- P_D: gates compute a1p(s+1) || units do cell2
        if (gateT) {
            const float* xn = &xbuf[(lo + 1) * INP];    // x(s+1)
            float4 xa = *(const float4*)(xn);
            float4 xb = *(const float4*)(xn + 4);
            u64 a0 = ffma2(wx[0], pk2(xa.x, xa.y), pk2(bb1, 0.0f));
            u64 a1 = ffma2(wx[1], pk2(xa.z, xa.w), pk2(w6 * xb.z, 0.0f));
            a0 = ffma2(wx[2], pk2(xb.x, xb.y), a0);
            const float4* hv = (const float4*)sh1;
            #pragma unroll
            for (int j = 0; j < 13; ++j) {
                float4 h = hv[j];
                a0 = ffma2(wh1[2*j],     pk2(h.x, h.y), a0);
                a1 = ffma2(wh1[2*j + 1], pk2(h.z, h.w), a1);
            }
            float2 f0 = upk2(a0), f1 = upk2(a1);
            a1p = (f0.x + f1.x) + (f0.y + f1.y);
            x7prev = xbuf[lo * INP + 7];               // x(s)[7] for next err
        }
        if (unitT) {
            float I = sg[u], F = sg[u + 50], G = sg[u + 100], O = sg[u + 150];
            c2 = F * c2 + I * G;
            sh2[u] = O * tanha(c2);
        }
        __syncthreads();   // BAR_D: h2(s) final
    }

    // epilogue: y(T-1)
    if (t == 0) {
        float y = bo;
        for (int j = 0; j < HDIM; ++j) y += swout[j] * sh2[j];
        out[T - 1] = y;
    }
}

extern "C" void kernel_launch(void* const* d_in, const int* in_sizes, int n_in,
                              void* d_out, int out_size) {
    const int T = in_sizes[0] / INP;
    lstm_r6_kernel<<<1, NTHREADS>>>(
        (const float*)d_in[0],
        (const float*)d_in[1], (const float*)d_in[2],
        (const float*)d_in[3], (const float*)d_in[4],
        (const float*)d_in[5], (const float*)d_in[6],
        (const float*)d_in[7], (const float*)d_in[8],
        (const float*)d_in[9], (const float*)d_in[10],
        (float*)d_out, T);
}

// round 7
// speedup vs baseline: 1.7137x; 1.7137x over previous
#include <cuda_runtime.h>

// 2-layer LSTM (H=50), T=65536 serial steps, one persistent CTA, 224 threads.
// Shuffle-quad layout: lane l of warp w owns gate kind k=l>>3 of unit
// u = w*8 + (l&7). The 4 gates of a unit live in ONE warp -> gate->cell
// handoff is 4 index-shuffles, no smem, no barrier. Cell state c is kept
// redundantly (identically) in all 4 lanes of the quad. Only 2 barriers/step:
//   Phase A: [y-dot + W_hh2@h2] over sh2 (shared LDS), err, g1=a1p+w7*err,
//            act, shfl, cell1 -> sh1
//   BAR_A
//   Phase B: [W_ih2@h1 (finish gates2) + W_hh1@h1 (a1p(s+1))] over sh1,
//            + W_ih1@x(s+1), act, shfl, cell2 -> sh2, cache x7
//   BAR_B

#define HDIM     50
#define INP      8
#define CHUNK    1024
#define NTHREADS 224

typedef unsigned long long u64;

__device__ __forceinline__ u64 pk2(float lo, float hi) {
    u64 r; asm("mov.b64 %0, {%1,%2};" : "=l"(r) : "f"(lo), "f"(hi)); return r;
}
__device__ __forceinline__ float2 upk2(u64 v) {
    float2 f; asm("mov.b64 {%0,%1}, %2;" : "=f"(f.x), "=f"(f.y) : "l"(v)); return f;
}
__device__ __forceinline__ u64 ffma2(u64 a, u64 b, u64 c) {
    u64 d; asm("fma.rn.f32x2 %0, %1, %2, %3;" : "=l"(d) : "l"(a), "l"(b), "l"(c)); return d;
}
__device__ __forceinline__ float tanha(float x) {
    float r; asm("tanh.approx.f32 %0, %1;" : "=f"(r) : "f"(x)); return r;
}

__global__ __launch_bounds__(NTHREADS, 1)
void lstm_r7_kernel(const float* __restrict__ input_seq,
                    const float* __restrict__ W_ih1, const float* __restrict__ W_hh1,
                    const float* __restrict__ b_ih1, const float* __restrict__ b_hh1,
                    const float* __restrict__ W_ih2, const float* __restrict__ W_hh2,
                    const float* __restrict__ b_ih2, const float* __restrict__ b_hh2,
                    const float* __restrict__ W_out, const float* __restrict__ b_out,
                    float* __restrict__ out, int T)
{
    __shared__ __align__(16) float sh1[52];    // h1(s), [50..51]=0
    __shared__ __align__(16) float sh2[52];    // h2(s), [50..51]=0
    __shared__ __align__(16) float swout[52];  // W_out padded
    __shared__ __align__(16) float xbuf[(CHUNK + 1) * INP];

    const int t = threadIdx.x;
    const int w = t >> 5;
    const int l = t & 31;
    const int k = l >> 3;                 // gate kind: 0=i 1=f 2=g 3=o
    const int j0 = l & 7;                 // unit-within-warp
    const int uraw = w * 8 + j0;
    const bool uvalid = (uraw < HDIM);
    const int u = uvalid ? uraw : (HDIM - 1);
    const int row = k * HDIM + u;          // this lane's gate row

    // activation: g-gate (k==2) -> tanh; others -> sigmoid
    const float actK = (k == 2) ? 1.0f : 0.5f;
    const float actA = (k == 2) ? 0.0f : 0.5f;

    // ---- per-thread full-row weights (f32x2 packed; [25] = zero pad)
    u64 wx[3], wh1[26], wi2[26], wh2[26];
    float w6, w7, bb1, bb2;
    {
        const float* r1 = W_ih1 + row * INP;
        wx[0] = pk2(r1[0], r1[1]);
        wx[1] = pk2(r1[2], r1[3]);
        wx[2] = pk2(r1[4], r1[5]);
        w6 = r1[6]; w7 = r1[7];
        const float* r2 = W_hh1 + row * HDIM;
        const float* r3 = W_ih2 + row * HDIM;
        const float* r4 = W_hh2 + row * HDIM;
        #pragma unroll
        for (int j = 0; j < 25; ++j) {
            wh1[j] = pk2(r2[2*j], r2[2*j+1]);
            wi2[j] = pk2(r3[2*j], r3[2*j+1]);
            wh2[j] = pk2(r4[2*j], r4[2*j+1]);
        }
        wh1[25] = 0ULL; wi2[25] = 0ULL; wh2[25] = 0ULL;
        bb1 = b_ih1[row] + b_hh1[row];
        bb2 = b_ih2[row] + b_hh2[row];
    }
    const float bo = b_out[0];
    if (t < 52) {
        swout[t] = (t < HDIM) ? W_out[t] : 0.0f;
        sh1[t] = 0.0f;
        sh2[t] = 0.0f;
    }

    float c1 = 0.0f, c2 = 0.0f, err = 0.0f, x7prev = 0.0f, a1p = 0.0f;
    __syncthreads();

    #pragma unroll 1
    for (int s = 0; s < T; ++s) {
        const int lo = s & (CHUNK - 1);
        if (lo == 0) {
            // old xbuf fully consumed at BAR_B of step s-1
            const float4* src = (const float4*)(input_seq + (size_t)s * INP);
            float4* dst = (float4*)xbuf;
            int n4 = (CHUNK + 1) * 2;
            int rem4 = (T - s) * 2;
            if (rem4 < n4) n4 = rem4;
            for (int i = t; i < n4; i += NTHREADS) dst[i] = src[i];
            __syncthreads();
            if (s == 0) {
                // bootstrap a1p(0) = bb1 + W_ih1 @ x(0)[0..6]  (h1(-1)=0)
                float4 xa = *(const float4*)(xbuf);
                float4 xb = *(const float4*)(xbuf + 4);
                u64 a0 = ffma2(wx[0], pk2(xa.x, xa.y), pk2(bb1, 0.0f));
                u64 a1 = ffma2(wx[1], pk2(xa.z, xa.w), pk2(w6 * xb.z, 0.0f));
                a0 = ffma2(wx[2], pk2(xb.x, xb.y), a0);
                float2 f0 = upk2(a0), f1 = upk2(a1);
                a1p = (f0.x + f1.x) + (f0.y + f1.y);
            }
        }

        // ================= Phase A =================
        // one pass over sh2 feeds y-dot AND W_hh2 @ h2(s-1)
        u64 y0 = pk2(0.0f, 0.0f), y1 = pk2(0.0f, 0.0f);
        u64 q0 = pk2(bb2, 0.0f),  q1 = pk2(0.0f, 0.0f);
        {
            const float4* hv = (const float4*)sh2;
            const float4* wv = (const float4*)swout;
            #pragma unroll
            for (int j = 0; j < 13; ++j) {
                float4 h = hv[j];
                float4 wq = wv[j];
                u64 hl = pk2(h.x, h.y), hh = pk2(h.z, h.w);
                y0 = ffma2(pk2(wq.x, wq.y), hl, y0);
                y1 = ffma2(pk2(wq.z, wq.w), hh, y1);
                q0 = ffma2(wh2[2*j],     hl, q0);
                q1 = ffma2(wh2[2*j + 1], hh, q1);
            }
        }
        {
            float2 f0 = upk2(y0), f1 = upk2(y1);
            float y = bo + (f0.x + f1.x) + (f0.y + f1.y);     // y(s-1)
            err = (s != 0) ? fmaf(0.1f, x7prev - y, 0.9f * err) : 0.0f;
            if (t == 0 && s != 0) out[s - 1] = y;
        }
        // gates1 finish + activation + quad shuffle + cell1
        {
            float g1 = fmaf(w7, err, a1p);
            float v0 = fmaf(tanha(actK * g1), actK, actA);
            float I = __shfl_sync(0xffffffffu, v0, j0);
            float F = __shfl_sync(0xffffffffu, v0, j0 + 8);
            float G = __shfl_sync(0xffffffffu, v0, j0 + 16);
            float O = __shfl_sync(0xffffffffu, v0, j0 + 24);
            c1 = fmaf(F, c1, I * G);
            float h1v = O * tanha(c1);
            if (k == 0 && uvalid) sh1[u] = h1v;
        }
        __syncthreads();   // BAR_A: h1(s) ready

        // ================= Phase B =================
        // one pass over sh1 feeds W_ih2@h1 (gates2) AND W_hh1@h1 (a1p(s+1))
        const float* xn = &xbuf[(lo + 1) * INP];               // x(s+1)
        float4 xa = *(const float4*)(xn);
        float4 xb = *(const float4*)(xn + 4);
        u64 a0 = ffma2(wx[0], pk2(xa.x, xa.y), pk2(bb1, 0.0f));
        u64 a1 = ffma2(wx[1], pk2(xa.z, xa.w), pk2(w6 * xb.z, 0.0f));
        a0 = ffma2(wx[2], pk2(xb.x, xb.y), a0);
        u64 r0 = pk2(0.0f, 0.0f), r1 = pk2(0.0f, 0.0f);
        {
            const float4* hv = (const float4*)sh1;
            #pragma unroll
            for (int j = 0; j < 13; ++j) {
                float4 h = hv[j];
                u64 hl = pk2(h.x, h.y), hh = pk2(h.z, h.w);
                r0 = ffma2(wi2[2*j],     hl, r0);
                r1 = ffma2(wi2[2*j + 1], hh, r1);
                a0 = ffma2(wh1[2*j],     hl, a0);
                a1 = ffma2(wh1[2*j + 1], hh, a1);
            }
        }
        {
            float2 f0 = upk2(q0), f1 = upk2(q1), f2 = upk2(r0), f3 = upk2(r1);
            float g2 = ((f0.x + f1.x) + (f0.y + f1.y)) + ((f2.x + f3.x) + (f2.y + f3.y));
            float2 g0 = upk2(a0), g1c = upk2(a1);
            a1p = (g0.x + g1c.x) + (g0.y + g1c.y);
            float v0 = fmaf(tanha(actK * g2), actK, actA);
            float I = __shfl_sync(0xffffffffu, v0, j0);
            float F = __shfl_sync(0xffffffffu, v0, j0 + 8);
            float G = __shfl_sync(0xffffffffu, v0, j0 + 16);
            float O = __shfl_sync(0xffffffffu, v0, j0 + 24);
            c2 = fmaf(F, c2, I * G);
            float h2v = O * tanha(c2);
            if (k == 0 && uvalid) sh2[u] = h2v;
        }
        x7prev = xbuf[lo * INP + 7];                           // x(s)[7]
        __syncthreads();   // BAR_B: h2(s) ready
    }

    // epilogue: y(T-1) from final h2
    if (t == 0) {
        float y = bo;
        for (int j = 0; j < HDIM; ++j) y += swout[j] * sh2[j];
        out[T - 1] = y;
    }
}

extern "C" void kernel_launch(void* const* d_in, const int* in_sizes, int n_in,
                              void* d_out, int out_size) {
    const int T = in_sizes[0] / INP;
    lstm_r7_kernel<<<1, NTHREADS>>>(
        (const float*)d_in[0],
        (const float*)d_in[1], (const float*)d_in[2],
        (const float*)d_in[3], (const float*)d_in[4],
        (const float*)d_in[5], (const float*)d_in[6],
        (const float*)d_in[7], (const float*)d_in[8],
        (const float*)d_in[9], (const float*)d_in[10],
        (float*)d_out, T);
}

// round 8
// speedup vs baseline: 1.7263x; 1.0074x over previous
#include <cuda_runtime.h>

// 2-layer LSTM (H=50), T=65536 serial steps, one persistent CTA, 224 threads.
// R7 shuffle-quad skeleton (lane l of warp w owns gate kind k=l>>3 of unit
// u=w*8+(l&7); 4 gates of a unit in one warp; cell state replicated in the
// quad; 2 barriers/step) with shorter chains:
//   - 4-way ILP in on-path dots (depth 7), packed f32x2 tail adds
//   - activation pre-scale folded into weights (no mul before tanh)
//   - x(s+1) loads + W_ih1@x FMAs hoisted into Phase A
//   - x7 carried from the xb.w register (no extra LDS)

#define HDIM     50
#define INP      8
#define CHUNK    1024
#define NTHREADS 224

typedef unsigned long long u64;

__device__ __forceinline__ u64 pk2(float lo, float hi) {
    u64 r; asm("mov.b64 %0, {%1,%2};" : "=l"(r) : "f"(lo), "f"(hi)); return r;
}
__device__ __forceinline__ float2 upk2(u64 v) {
    float2 f; asm("mov.b64 {%0,%1}, %2;" : "=f"(f.x), "=f"(f.y) : "l"(v)); return f;
}
__device__ __forceinline__ u64 ffma2(u64 a, u64 b, u64 c) {
    u64 d; asm("fma.rn.f32x2 %0, %1, %2, %3;" : "=l"(d) : "l"(a), "l"(b), "l"(c)); return d;
}
__device__ __forceinline__ u64 add2(u64 a, u64 b) {
    u64 d; asm("add.rn.f32x2 %0, %1, %2;" : "=l"(d) : "l"(a), "l"(b)); return d;
}
__device__ __forceinline__ float tanha(float x) {
    float r; asm("tanh.approx.f32 %0, %1;" : "=f"(r) : "f"(x)); return r;
}

__global__ __launch_bounds__(NTHREADS, 1)
void lstm_r8_kernel(const float* __restrict__ input_seq,
                    const float* __restrict__ W_ih1, const float* __restrict__ W_hh1,
                    const float* __restrict__ b_ih1, const float* __restrict__ b_hh1,
                    const float* __restrict__ W_ih2, const float* __restrict__ W_hh2,
                    const float* __restrict__ b_ih2, const float* __restrict__ b_hh2,
                    const float* __restrict__ W_out, const float* __restrict__ b_out,
                    float* __restrict__ out, int T)
{
    __shared__ __align__(16) float sh1[52];    // h1(s), [50..51]=0
    __shared__ __align__(16) float sh2[52];    // h2(s), [50..51]=0
    __shared__ __align__(16) float swout[52];  // W_out padded
    __shared__ __align__(16) float xbuf[(CHUNK + 1) * INP];

    const int t = threadIdx.x;
    const int w = t >> 5;
    const int l = t & 31;
    const int k = l >> 3;                 // gate kind: 0=i 1=f 2=g 3=o
    const int j0 = l & 7;                 // unit-within-warp
    const int uraw = w * 8 + j0;
    const bool uvalid = (uraw < HDIM);
    const int u = uvalid ? uraw : (HDIM - 1);
    const int row = k * HDIM + u;

    // activation: act(x) = fmaf(tanha(K*x), K, A); K folded into the weights
    const float actK = (k == 2) ? 1.0f : 0.5f;
    const float actA = (k == 2) ? 0.0f : 0.5f;

    // ---- per-thread full-row weights, pre-scaled by actK (f32x2; [25]=pad)
    u64 wx[3], wh1[26], wi2[26], wh2[26];
    float w6K, w7K, bb1K, bb2K;
    {
        const float* r1 = W_ih1 + row * INP;
        wx[0] = pk2(actK * r1[0], actK * r1[1]);
        wx[1] = pk2(actK * r1[2], actK * r1[3]);
        wx[2] = pk2(actK * r1[4], actK * r1[5]);
        w6K = actK * r1[6]; w7K = actK * r1[7];
        const float* r2 = W_hh1 + row * HDIM;
        const float* r3 = W_ih2 + row * HDIM;
        const float* r4 = W_hh2 + row * HDIM;
        #pragma unroll
        for (int j = 0; j < 25; ++j) {
            wh1[j] = pk2(actK * r2[2*j], actK * r2[2*j+1]);
            wi2[j] = pk2(actK * r3[2*j], actK * r3[2*j+1]);
            wh2[j] = pk2(actK * r4[2*j], actK * r4[2*j+1]);
        }
        wh1[25] = 0ULL; wi2[25] = 0ULL; wh2[25] = 0ULL;
        bb1K = actK * (b_ih1[row] + b_hh1[row]);
        bb2K = actK * (b_ih2[row] + b_hh2[row]);
    }
    const float bo = b_out[0];
    if (t < 52) {
        swout[t] = (t < HDIM) ? W_out[t] : 0.0f;
        sh1[t] = 0.0f;
        sh2[t] = 0.0f;
    }

    float c1 = 0.0f, c2 = 0.0f, err = 0.0f, a1p = 0.0f;
    float x7_use = 0.0f, x7_next = 0.0f;
    __syncthreads();

    #pragma unroll 1
    for (int s = 0; s < T; ++s) {
        const int lo = s & (CHUNK - 1);
        if (lo == 0) {
            // old xbuf fully consumed at BAR_B of step s-1
            const float4* src = (const float4*)(input_seq + (size_t)s * INP);
            float4* dst = (float4*)xbuf;
            int n4 = (CHUNK + 1) * 2;
            int rem4 = (T - s) * 2;
            if (rem4 < n4) n4 = rem4;
            for (int i = t; i < n4; i += NTHREADS) dst[i] = src[i];
            __syncthreads();
            if (s == 0) {
                // bootstrap a1p(0) = K*(bb1 + W_ih1 @ x(0)[0..6]); x7_next = x(0)[7]
                float4 xa = *(const float4*)(xbuf);
                float4 xb = *(const float4*)(xbuf + 4);
                u64 a0 = ffma2(wx[0], pk2(xa.x, xa.y), pk2(bb1K, 0.0f));
                u64 a1 = ffma2(wx[1], pk2(xa.z, xa.w), pk2(w6K * xb.z, 0.0f));
                a0 = ffma2(wx[2], pk2(xb.x, xb.y), a0);
                float2 f = upk2(add2(a0, a1));
                a1p = f.x + f.y;
                x7_next = xb.w;
            }
        }

        // ================= Phase A =================
        // x(s+1) early loads + W_ih1@x FMAs (off-path; carried into Phase B)
        const float* xn = &xbuf[(lo + 1) * INP];
        float4 xa = *(const float4*)(xn);
        float4 xb = *(const float4*)(xn + 4);
        u64 a0 = ffma2(wx[0], pk2(xa.x, xa.y), pk2(bb1K, 0.0f));
        u64 a1 = ffma2(wx[1], pk2(xa.z, xa.w), pk2(w6K * xb.z, 0.0f));
        a0 = ffma2(wx[2], pk2(xb.x, xb.y), a0);

        // one pass over sh2 feeds y-dot AND W_hh2 @ h2(s-1); 4 ILP chains each
        u64 y0 = pk2(bo, 0.0f), y1 = pk2(0.0f, 0.0f), y2 = y1, y3 = y1;
        u64 q0 = pk2(bb2K, 0.0f), q1 = y1, q2 = y1, q3 = y1;
        {
            const float4* hv = (const float4*)sh2;
            const float4* wv = (const float4*)swout;
            #pragma unroll
            for (int j = 0; j < 6; ++j) {
                float4 ha = hv[2*j],   wa = wv[2*j];
                float4 hb = hv[2*j+1], wb = wv[2*j+1];
                u64 hal = pk2(ha.x, ha.y), hah = pk2(ha.z, ha.w);
                u64 hbl = pk2(hb.x, hb.y), hbh = pk2(hb.z, hb.w);
                y0 = ffma2(pk2(wa.x, wa.y), hal, y0);
                y1 = ffma2(pk2(wa.z, wa.w), hah, y1);
                y2 = ffma2(pk2(wb.x, wb.y), hbl, y2);
                y3 = ffma2(pk2(wb.z, wb.w), hbh, y3);
                q0 = ffma2(wh2[4*j],     hal, q0);
                q1 = ffma2(wh2[4*j + 1], hah, q1);
                q2 = ffma2(wh2[4*j + 2], hbl, q2);
                q3 = ffma2(wh2[4*j + 3], hbh, q3);
            }
            float4 hc = hv[12], wc = wv[12];
            u64 hcl = pk2(hc.x, hc.y), hch = pk2(hc.z, hc.w);
            y0 = ffma2(pk2(wc.x, wc.y), hcl, y0);
            y1 = ffma2(pk2(wc.z, wc.w), hch, y1);
            q0 = ffma2(wh2[24], hcl, q0);
            q1 = ffma2(wh2[25], hch, q1);
        }
        // y, err, gates1, cell1
        {
            float2 yf = upk2(add2(add2(y0, y1), add2(y2, y3)));
            float y = yf.x + yf.y;                              // y(s-1)
            err = (s != 0) ? fmaf(0.1f, x7_use - y, 0.9f * err) : 0.0f;
            if (t == 0 && s != 0) out[s - 1] = y;
            float g1K = fmaf(w7K, err, a1p);
            float v0 = fmaf(tanha(g1K), actK, actA);
            float I = __shfl_sync(0xffffffffu, v0, j0);
            float F = __shfl_sync(0xffffffffu, v0, j0 + 8);
            float G = __shfl_sync(0xffffffffu, v0, j0 + 16);
            float O = __shfl_sync(0xffffffffu, v0, j0 + 24);
            c1 = fmaf(F, c1, I * G);
            float h1v = O * tanha(c1);
            if (k == 0 && uvalid) sh1[u] = h1v;
        }
        __syncthreads();   // BAR_A: h1(s) ready

        // ================= Phase B =================
        // one pass over sh1 feeds W_ih2@h1 (4 chains) AND W_hh1@h1 (2 chains)
        u64 r0 = pk2(0.0f, 0.0f), r1 = r0, r2 = r0, r3 = r0;
        {
            const float4* hv = (const float4*)sh1;
            #pragma unroll
            for (int j = 0; j < 6; ++j) {
                float4 ha = hv[2*j];
                float4 hb = hv[2*j+1];
                u64 hal = pk2(ha.x, ha.y), hah = pk2(ha.z, ha.w);
                u64 hbl = pk2(hb.x, hb.y), hbh = pk2(hb.z, hb.w);
                r0 = ffma2(wi2[4*j],     hal, r0);
                r1 = ffma2(wi2[4*j + 1], hah, r1);
                r2 = ffma2(wi2[4*j + 2], hbl, r2);
                r3 = ffma2(wi2[4*j + 3], hbh, r3);
                a0 = ffma2(wh1[4*j],     hal, a0);
                a1 = ffma2(wh1[4*j + 1], hah, a1);
                a0 = ffma2(wh1[4*j + 2], hbl, a0);
                a1 = ffma2(wh1[4*j + 3], hbh, a1);
            }
            float4 hc = hv[12];
            u64 hcl = pk2(hc.x, hc.y), hch = pk2(hc.z, hc.w);
            r0 = ffma2(wi2[24], hcl, r0);
            r1 = ffma2(wi2[25], hch, r1);
            a0 = ffma2(wh1[24], hcl, a0);
            a1 = ffma2(wh1[25], hch, a1);
        }
        {
            // g2K = sum of q-chains + r-chains (already K-scaled)
            u64 m = add2(add2(add2(q0, q1), add2(q2, q3)),
                         add2(add2(r0, r1), add2(r2, r3)));
            float2 mf = upk2(m);
            float g2K = mf.x + mf.y;
            float2 af = upk2(add2(a0, a1));
            a1p = af.x + af.y;                                  // K*gates1-partial(s+1)
            float v0 = fmaf(tanha(g2K), actK, actA);
            float I = __shfl_sync(0xffffffffu, v0, j0);
            float F = __shfl_sync(0xffffffffu, v0, j0 + 8);
            float G = __shfl_sync(0xffffffffu, v0, j0 + 16);
            float O = __shfl_sync(0xffffffffu, v0, j0 + 24);
            c2 = fmaf(F, c2, I * G);
            float h2v = O * tanha(c2);
            if (k == 0 && uvalid) sh2[u] = h2v;
        }
        x7_use = x7_next;          // x7(s-1) -> used at Phase A(s+1): x7(s)
        x7_next = xb.w;            // x7(s+1)
        __syncthreads();   // BAR_B: h2(s) ready
    }

    // epilogue: y(T-1) from final h2
    if (t == 0) {
        float y = bo;
        for (int j = 0; j < HDIM; ++j) y += swout[j] * sh2[j];
        out[T - 1] = y;
    }
}

extern "C" void kernel_launch(void* const* d_in, const int* in_sizes, int n_in,
                              void* d_out, int out_size) {
    const int T = in_sizes[0] / INP;
    lstm_r8_kernel<<<1, NTHREADS>>>(
        (const float*)d_in[0],
        (const float*)d_in[1], (const float*)d_in[2],
        (const float*)d_in[3], (const float*)d_in[4],
        (const float*)d_in[5], (const float*)d_in[6],
        (const float*)d_in[7], (const float*)d_in[8],
        (const float*)d_in[9], (const float*)d_in[10],
        (float*)d_out, T);
}